// round 17
// baseline (speedup 1.0000x reference)
#include <cuda_runtime.h>
#include <cuda_fp16.h>
#include <cstdint>

// Problem constants: B=4, N=256, D=128, M=128, C=128
#define BB 4
#define NN 256
#define DD 128
#define MM 128
#define CC 128
#define NBLK 512

// Scratch (device globals — no allocation allowed)
// g_pjb PRE-SCALED by 0.5, stored as __half:
// hx = pi + pjb = pre/2 ; silu(pre) = hx + hx*tanh(hx)
__device__ __align__(16) __half g_pjb[BB * NN * MM];
__device__ float g_W2c[MM * MM];   // W2 @ Wc1
__device__ float g_b2c[MM];        // b2 @ Wc1

// Tree grid barrier: 16 padded group counters (32 arrivals each) + master.
// gen persists across graph replays; compared by equality -> deterministic.
__device__ unsigned int g_cnt[16 * 32];   // one counter per 128B line
__device__ unsigned int g_master = 0;
__device__ volatile unsigned int g_gen = 0;

__device__ __forceinline__ void grid_barrier(int blk) {
    __syncthreads();
    if (threadIdx.x == 0) {
        __threadfence();
        const unsigned int my = g_gen;
        if (atomicAdd(&g_cnt[(blk & 15) * 32], 1u) == 31u) {
            g_cnt[(blk & 15) * 32] = 0;
            __threadfence();
            if (atomicAdd(&g_master, 1u) == 15u) {
                g_master = 0;
                __threadfence();
                g_gen = my + 1;
            }
        }
        while (g_gen == my) { }
        __threadfence();
    }
    __syncthreads();
}

__device__ __forceinline__ __half2 tanh2(__half2 x) {
    unsigned r, i = *reinterpret_cast<unsigned*>(&x);
    asm("tanh.approx.f16x2 %0, %1;" : "=r"(r) : "r"(i));
    return *reinterpret_cast<__half2*>(&r);
}
__device__ __forceinline__ float siluf(float x) {
    return __fdividef(x, 1.0f + __expf(-x));
}
__device__ __forceinline__ void cp16(unsigned int dst, const void* src) {
    asm volatile("cp.async.cg.shared.global [%0], [%1], 16;" :: "r"(dst), "l"(src));
}
#define CP_COMMIT()   asm volatile("cp.async.commit_group;")
#define CP_WAIT(n)    asm volatile("cp.async.wait_group %0;" :: "n"(n))

__device__ __forceinline__ void fma4(float4& a, float s, const float4& w) {
    a.x = fmaf(s, w.x, a.x);
    a.y = fmaf(s, w.y, a.y);
    a.z = fmaf(s, w.z, a.z);
    a.w = fmaf(s, w.w, a.w);
}

// ---------------------------------------------------------------------------
// ONE persistent kernel: 512 blocks x 256 threads, all resident (lb(256,4)).
// Phase 0 BALANCED: every block does projection(2 rows) + W2c quarter-row;
// b2c spread (1 col per (blk&3)==3 block). pi kept in smem (g_pi deleted).
// ---------------------------------------------------------------------------
__global__ void __launch_bounds__(256, 4) fused_kernel(
    const float* __restrict__ h,
    const float* __restrict__ adj,
    const float* __restrict__ W1a,
    const float* __restrict__ W1b,
    const float* __restrict__ b1,
    const float* __restrict__ W2,
    const float* __restrict__ b2,
    const float* __restrict__ Wc1,
    const float* __restrict__ bc1,
    const float* __restrict__ Wc2,
    const float* __restrict__ bc2,
    float* __restrict__ out)
{
    const int t    = threadIdx.x;
    const int blk  = blockIdx.x;       // 0..511
    const int lane = t & 31;
    const int w    = t >> 5;           // warp id = group id 0..7
    const int col0 = lane * 4;         // this thread's col quad

    __shared__ uint4 ring4[8][4][32];  // 16KB: phase-0/epi scratch + phase-1 ring
    __shared__ __half2 adjh2[2][NN];   // 2KB diag-masked weights (half2)
    __shared__ float wsum[2][8];
    __shared__ float sacc[2][MM];
    __shared__ float shid[2][MM];
    __shared__ float hsh[2][DD];       // phase 0 rows / W2 row
    __shared__ __align__(16) __half pish[2][MM];  // this block's pi rows (fp16)

    float* scr = reinterpret_cast<float*>(ring4);   // 16KB scratch view

    // ================= Phase 0 =================
    // Projection rows 2*blk, 2*blk+1.
    // Thread = (col quad, d-group of 16): 32 LDG.128 total for weights.
    {
        hsh[t >> 7][t & 127] = h[(size_t)blk * 256 + t];
        __syncthreads();
        float4 pa0 = {0,0,0,0}, pa1 = {0,0,0,0};
        float4 pp0 = {0,0,0,0}, pp1 = {0,0,0,0};
        const int d0 = w * 16;
        #pragma unroll
        for (int d = d0; d < d0 + 16; d++) {
            const float4 wa = *reinterpret_cast<const float4*>(W1a + d * MM + col0);
            const float4 wb = *reinterpret_cast<const float4*>(W1b + d * MM + col0);
            const float h0 = hsh[0][d];
            const float h1 = hsh[1][d];
            fma4(pa0, h0, wa);
            fma4(pa1, h1, wa);
            fma4(pp0, h0, wb);
            fma4(pp1, h1, wb);
        }
        float4* s4 = reinterpret_cast<float4*>(scr) + (w * 32 + lane) * 4;
        s4[0] = pa0; s4[1] = pa1; s4[2] = pp0; s4[3] = pp1;
        __syncthreads();
        // reduce: thread -> (q = t>>7, col = t&127); pi -> smem, pjb -> global
        {
            const int colr = t & 127;
            const int q    = t >> 7;
            float vpi = 0.f, vpj = 0.f;
            #pragma unroll
            for (int g = 0; g < 8; g++) {
                const int base = (g * 32 + (colr >> 2)) * 16 + (colr & 3);
                vpi += scr[base + q * 4];
                vpj += scr[base + (q + 2) * 4];
            }
            pish[q][colr] = __float2half(0.5f * vpi);
            g_pjb[(size_t)(blk * 2 + q) * MM + colr] =
                __float2half(0.5f * (vpj + b1[colr]));
        }
        // load W2 row for this block's W2c quarter (overlaps reduce)
        if (t < 128) hsh[0][t] = W2[(blk >> 2) * MM + t];
    }
    __syncthreads();

    // ---- W2c quarter-row: row = blk>>2, cols [(blk&3)*32, +32) ----
    {
        const int c0  = (blk & 3) * 32;
        const int colw = c0 + (t & 31);
        const int g   = t >> 5;           // term group 0..7 (16 terms each)
        float v = 0.f;
        #pragma unroll
        for (int l = g * 16; l < g * 16 + 16; l++)
            v = fmaf(hsh[0][l], Wc1[l * MM + colw], v);
        scr[g * 32 + (t & 31)] = v;
    }
    __syncthreads();
    if (t < 32) {
        float v = 0.f;
        #pragma unroll
        for (int g = 0; g < 8; g++) v += scr[g * 32 + t];
        g_W2c[(blk >> 2) * MM + (blk & 3) * 32 + t] = v;
    }
    // ---- b2c: one column per (blk&3)==3 block, on warp 1 ----
    if ((blk & 3) == 3 && w == 1) {
        const int colb = blk >> 2;
        const int l0 = lane * 4;
        float v = 0.f;
        #pragma unroll
        for (int k = 0; k < 4; k++)
            v = fmaf(b2[l0 + k], Wc1[(l0 + k) * MM + colb], v);
        #pragma unroll
        for (int o = 16; o; o >>= 1) v += __shfl_xor_sync(0xFFFFFFFFu, v, o);
        if (lane == 0) g_b2c[colb] = v;
    }

    // ---- adj prep: independent of phase 0, overlaps its tail ----
    const int b  = blk >> 7;
    const int i0 = (blk & 127) * 2;
    const float* arow0 = adj + ((size_t)(b * NN + i0)) * NN;
    const float* arow1 = arow0 + NN;
    {
        float a0 = arow0[t], a1 = arow1[t];
        adjh2[0][t] = __float2half2_rn((t == i0)     ? 0.0f : a0);
        adjh2[1][t] = __float2half2_rn((t == i0 + 1) ? 0.0f : a1);
        #pragma unroll
        for (int o = 16; o; o >>= 1) {
            a0 += __shfl_xor_sync(0xFFFFFFFFu, a0, o);
            a1 += __shfl_xor_sync(0xFFFFFFFFu, a1, o);
        }
        if (lane == 0) { wsum[0][w] = a0; wsum[1][w] = a1; }
    }
    const float ii0 = arow0[i0];
    const float ii1 = arow1[i0 + 1];

    grid_barrier(blk);

    // ================= Phase 1 =================
    float sum0 = 0.f, sum1 = 0.f;
    #pragma unroll
    for (int g = 0; g < 8; g++) { sum0 += wsum[0][g]; sum1 += wsum[1][g]; }
    const float S0   = sum0 - ii0;
    const float S1   = sum1 - ii1;
    const float inv0 = __fdividef(1.0f, fmaxf(sum0, 1.0f));
    const float inv1 = __fdividef(1.0f, fmaxf(sum1, 1.0f));

    const int rsel = lane >> 4;   // which row of the slot's pair
    const int esel = lane & 15;   // 16B chunk within a row (8 halfs)

    // pi chunk (8 halfs = 4 half2) for both i's — from smem (own rows!)
    __half2 piA[4], piB[4];
    {
        const uint4 ra = reinterpret_cast<const uint4*>(&pish[0][0])[esel];
        const uint4 rb = reinterpret_cast<const uint4*>(&pish[1][0])[esel];
        piA[0] = *reinterpret_cast<const __half2*>(&ra.x);
        piA[1] = *reinterpret_cast<const __half2*>(&ra.y);
        piA[2] = *reinterpret_cast<const __half2*>(&ra.z);
        piA[3] = *reinterpret_cast<const __half2*>(&ra.w);
        piB[0] = *reinterpret_cast<const __half2*>(&rb.x);
        piB[1] = *reinterpret_cast<const __half2*>(&rb.y);
        piB[2] = *reinterpret_cast<const __half2*>(&rb.z);
        piB[3] = *reinterpret_cast<const __half2*>(&rb.w);
    }

    // warp w owns rows [w*32, w*32+32); slot = 2 rows; lane owns its 16B
    const __half* srcbase = g_pjb + ((size_t)(b * NN) + w * 32 + rsel) * MM
                            + esel * 8;
    const unsigned int ring_lane =
        (unsigned int)__cvta_generic_to_shared(&ring4[w][0][0]) + lane * 16;
    const uint4* rd = &ring4[w][0][0];

    float2 fA[4] = {{0.f,0.f},{0.f,0.f},{0.f,0.f},{0.f,0.f}};
    float2 fB[4] = {{0.f,0.f},{0.f,0.f},{0.f,0.f},{0.f,0.f}};
    const __half2 hz = __float2half2_rn(0.f);
    __half2 hA[4] = {hz, hz, hz, hz};
    __half2 hB[4] = {hz, hz, hz, hz};

    // Prologue: 3 slots (6 rows) in flight
    #pragma unroll
    for (int s = 0; s < 3; s++) {
        cp16(ring_lane + s * 512, srcbase + 2 * s * MM);
        CP_COMMIT();
    }

    #pragma unroll
    for (int it = 0; it < 16; it++) {
        if (it <= 13)      { CP_WAIT(2); }
        else if (it == 14) { CP_WAIT(1); }
        else               { CP_WAIT(0); }

        const uint4 raw = rd[(it & 3) * 32 + lane];
        __half2 v[4];
        v[0] = *reinterpret_cast<const __half2*>(&raw.x);
        v[1] = *reinterpret_cast<const __half2*>(&raw.y);
        v[2] = *reinterpret_cast<const __half2*>(&raw.z);
        v[3] = *reinterpret_cast<const __half2*>(&raw.w);

        const __half2 wA2 = adjh2[0][w * 32 + 2 * it + rsel];
        const __half2 wB2 = adjh2[1][w * 32 + 2 * it + rsel];

        #pragma unroll
        for (int k = 0; k < 4; k++) {
            __half2 hxA = __hadd2(piA[k], v[k]);
            __half2 sA  = __hfma2(hxA, tanh2(hxA), hxA);
            hA[k] = __hfma2(wA2, sA, hA[k]);
            __half2 hxB = __hadd2(piB[k], v[k]);
            __half2 sB  = __hfma2(hxB, tanh2(hxB), hxB);
            hB[k] = __hfma2(wB2, sB, hB[k]);
        }

        // promote to fp32 every 4 iterations (4 fp16 terms per element)
        if ((it & 3) == 3) {
            #pragma unroll
            for (int k = 0; k < 4; k++) {
                float2 pa = __half22float2(hA[k]);
                float2 pb = __half22float2(hB[k]);
                fA[k].x += pa.x; fA[k].y += pa.y;
                fB[k].x += pb.x; fB[k].y += pb.y;
                hA[k] = hz; hB[k] = hz;
            }
        }

        if (it <= 12) {
            cp16(ring_lane + ((it + 3) & 3) * 512, srcbase + 2 * (it + 3) * MM);
            CP_COMMIT();
        }
    }

    // Combine the two half-warp row groups (same m-columns)
    #pragma unroll
    for (int k = 0; k < 4; k++) {
        fA[k].x += __shfl_xor_sync(0xFFFFFFFFu, fA[k].x, 16);
        fA[k].y += __shfl_xor_sync(0xFFFFFFFFu, fA[k].y, 16);
        fB[k].x += __shfl_xor_sync(0xFFFFFFFFu, fB[k].x, 16);
        fB[k].y += __shfl_xor_sync(0xFFFFFFFFu, fB[k].y, 16);
    }

    // All ring reads done -> overlay acc-reduction buffer [8][2][MM]
    __syncthreads();
    if (lane < 16) {
        float* dA = scr + (w * 2 + 0) * MM + esel * 8;
        float* dB = scr + (w * 2 + 1) * MM + esel * 8;
        *reinterpret_cast<float4*>(dA)     = make_float4(fA[0].x, fA[0].y, fA[1].x, fA[1].y);
        *reinterpret_cast<float4*>(dA + 4) = make_float4(fA[2].x, fA[2].y, fA[3].x, fA[3].y);
        *reinterpret_cast<float4*>(dB)     = make_float4(fB[0].x, fB[0].y, fB[1].x, fB[1].y);
        *reinterpret_cast<float4*>(dB + 4) = make_float4(fB[2].x, fB[2].y, fB[3].x, fB[3].y);
    }
    __syncthreads();

    // Reduce across warps: thread -> (ii = t>>7, col)
    {
        const int ii  = t >> 7;
        const int colr = t & 127;
        float s = 0.f;
        #pragma unroll
        for (int g = 0; g < 8; g++) s += scr[(g * 2 + ii) * MM + colr];
        sacc[ii][colr] = s;
    }
    __syncthreads();

    // ---- Epilogue stage 1: float4 weights, both i's per load ----
    {
        float4 vA = {0,0,0,0}, vB = {0,0,0,0};
        const int m0 = w * 16;
        #pragma unroll
        for (int m = m0; m < m0 + 16; m++) {
            const float4 wv = *reinterpret_cast<const float4*>(g_W2c + m * MM + col0);
            fma4(vA, sacc[0][m], wv);
            fma4(vB, sacc[1][m], wv);
        }
        float4* s4 = reinterpret_cast<float4*>(scr) + (w * 32 + lane) * 2;
        s4[0] = vA; s4[1] = vB;
    }
    __syncthreads();
    {
        const int ii  = t >> 7;
        const int colr = t & 127;
        float v = 0.f;
        #pragma unroll
        for (int g = 0; g < 8; g++)
            v += scr[(g * 32 + (colr >> 2)) * 8 + ii * 4 + (colr & 3)];
        const float Si   = ii ? S1 : S0;
        const float invi = ii ? inv1 : inv0;
        const float u = fmaf(v + Si * g_b2c[colr], invi, bc1[colr]);
        shid[ii][colr] = siluf(u);
    }
    __syncthreads();

    // ---- Epilogue stage 2: float4 weights, both i's per load ----
    {
        float4 vA = {0,0,0,0}, vB = {0,0,0,0};
        const int m0 = w * 16;
        #pragma unroll
        for (int m = m0; m < m0 + 16; m++) {
            const float4 wv = *reinterpret_cast<const float4*>(Wc2 + m * CC + col0);
            fma4(vA, shid[0][m], wv);
            fma4(vB, shid[1][m], wv);
        }
        float4* s4 = reinterpret_cast<float4*>(scr) + (w * 32 + lane) * 2;
        s4[0] = vA; s4[1] = vB;
    }
    __syncthreads();
    {
        const int ii  = t >> 7;
        const int colr = t & 127;
        float v = 0.f;
        #pragma unroll
        for (int g = 0; g < 8; g++)
            v += scr[(g * 32 + (colr >> 2)) * 8 + ii * 4 + (colr & 3)];
        out[((size_t)(b * NN + i0 + ii)) * CC + colr] = v + bc2[colr];
    }
}

// ---------------------------------------------------------------------------
// Launch
// ---------------------------------------------------------------------------
extern "C" void kernel_launch(void* const* d_in, const int* in_sizes, int n_in,
                              void* d_out, int out_size)
{
    const float* h   = (const float*)d_in[0];
    const float* adj = (const float*)d_in[1];
    const float* W1a = (const float*)d_in[2];
    const float* W1b = (const float*)d_in[3];
    const float* b1  = (const float*)d_in[4];
    const float* W2  = (const float*)d_in[5];
    const float* b2  = (const float*)d_in[6];
    const float* Wc1 = (const float*)d_in[7];
    const float* bc1 = (const float*)d_in[8];
    const float* Wc2 = (const float*)d_in[9];
    const float* bc2 = (const float*)d_in[10];
    float* out = (float*)d_out;

    fused_kernel<<<NBLK, 256>>>(h, adj, W1a, W1b, b1, W2, b2, Wc1,
                                bc1, Wc2, bc2, out);
}